// round 12
// baseline (speedup 1.0000x reference)
#include <cuda_runtime.h>
#include <cuda_bf16.h>
#include <cuda_fp16.h>
#include <mma.h>
#include <cstdint>

using namespace nvcuda;

#define NNODES 100000
#define NEDGES 1600000
#define FIN    256
#define HD1    64
#define H1H    8
#define C2     40
#define C2P    48

// ---------------- scratch (static device globals) ---------------------------
__device__ __half g_h1h[NNODES * HD1];           // layer-1 features, fp16
__device__ __half g_acth[(NNODES + 128) * HD1];  // ELU activations (pad rows zero)
__device__ float g_s1src[NNODES * H1H];
__device__ float g_s1dst[NNODES * H1H];
__device__ __half g_h2h[NNODES * C2];            // layer-2 features, fp16
__device__ float g_s2src[NNODES];
__device__ float g_s2dst[NNODES];
__device__ int   g_deg[NNODES];
__device__ int   g_off[NNODES + 1];
__device__ int   g_pos[NNODES];
__device__ int   g_srcs[NEDGES];
__device__ int   g_bsum[128];
__device__ int   g_bpre[128];

// ---------------- K1: tf32 WMMA GEMM1 + fused s1 scores ---------------------
// h1[128,64] = x_tile[128,256] @ W1[256,64], single-pass tf32 (m16n16k8).
#define LDA 72                       // fp32 elems per staged row (64 + 8 pad)
#define OFF_A 0                      // A: 128*72*4 = 36864 B (Cs reuses this)
#define OFF_B 36864                  // B: 64*72*4  = 18432 B
#define GEMM_SMEM 55296

__global__ void __launch_bounds__(256, 3) k_gemm1_tc(
        const float* __restrict__ x, const float* __restrict__ W1,
        const float* __restrict__ a1_src, const float* __restrict__ a1_dst, int n) {
    extern __shared__ char smem[];
    float* As = (float*)(smem + OFF_A);
    float* Bs = (float*)(smem + OFF_B);
    float* Cs = (float*)(smem + OFF_A);   // reused after last MMA

    int tid = threadIdx.x, warp = tid >> 5;
    int brow = blockIdx.x * 128;
    int m0 = (warp >> 1) * 32;
    int n0 = (warp & 1) * 32;

    wmma::fragment<wmma::accumulator, 16, 16, 8, float> acc[2][2];
#pragma unroll
    for (int i = 0; i < 2; i++)
#pragma unroll
        for (int j = 0; j < 2; j++) wmma::fill_fragment(acc[i][j], 0.f);

    for (int chunk = 0; chunk < 4; chunk++) {
        int k0 = chunk * 64;
        // stage A: 128 rows x 64 fp32 (raw, no conversion)
#pragma unroll
        for (int t = 0; t < 8; t++) {
            int idx = tid + t * 256;
            int r = idx >> 4, q = idx & 15;
            int grow = brow + r;
            float4 v = make_float4(0.f, 0.f, 0.f, 0.f);
            if (grow < n) v = *(const float4*)(x + (size_t)grow * FIN + k0 + q * 4);
            *(float4*)(As + r * LDA + q * 4) = v;
        }
        // stage B: 64 k-rows x 64 fp32
#pragma unroll
        for (int t = 0; t < 4; t++) {
            int idx = tid + t * 256;
            int k = idx >> 4, q = idx & 15;
            *(float4*)(Bs + k * LDA + q * 4) =
                *(const float4*)(W1 + (size_t)(k0 + k) * HD1 + q * 4);
        }
        __syncthreads();

#pragma unroll
        for (int k8 = 0; k8 < 8; k8++) {
            wmma::fragment<wmma::matrix_a, 16, 16, 8, wmma::precision::tf32, wmma::row_major> af[2];
            wmma::fragment<wmma::matrix_b, 16, 16, 8, wmma::precision::tf32, wmma::row_major> bf[2];
#pragma unroll
            for (int i = 0; i < 2; i++) {
                wmma::load_matrix_sync(af[i], As + (m0 + 16 * i) * LDA + k8 * 8, LDA);
#pragma unroll
                for (int t2 = 0; t2 < af[i].num_elements; t2++)
                    af[i].x[t2] = wmma::__float_to_tf32(af[i].x[t2]);
            }
#pragma unroll
            for (int j = 0; j < 2; j++) {
                wmma::load_matrix_sync(bf[j], Bs + (k8 * 8) * LDA + n0 + 16 * j, LDA);
#pragma unroll
                for (int t2 = 0; t2 < bf[j].num_elements; t2++)
                    bf[j].x[t2] = wmma::__float_to_tf32(bf[j].x[t2]);
            }
#pragma unroll
            for (int i = 0; i < 2; i++)
#pragma unroll
                for (int j = 0; j < 2; j++)
                    wmma::mma_sync(acc[i][j], af[i], bf[j], acc[i][j]);
        }
        __syncthreads();
    }

#pragma unroll
    for (int i = 0; i < 2; i++)
#pragma unroll
        for (int j = 0; j < 2; j++)
            wmma::store_matrix_sync(Cs + (m0 + 16 * i) * LDA + n0 + 16 * j,
                                    acc[i][j], LDA, wmma::mem_row_major);
    __syncthreads();

    // epilogue: h1 fp16 + fused s1 scores. thread t: row t>>1, half t&1.
    {
        int r = tid >> 1, half = tid & 1;
        int row = brow + r;
        if (row < n) {
            const float* cr = Cs + r * LDA + half * 32;
            float vals[32];
            uint32_t packed[16];
#pragma unroll
            for (int q = 0; q < 8; q++) {
                float4 v = *(const float4*)(cr + q * 4);
                vals[q * 4 + 0] = v.x; vals[q * 4 + 1] = v.y;
                vals[q * 4 + 2] = v.z; vals[q * 4 + 3] = v.w;
                __half2 p0 = __floats2half2_rn(v.x, v.y);
                __half2 p1 = __floats2half2_rn(v.z, v.w);
                memcpy(&packed[q * 2], &p0, 4);
                memcpy(&packed[q * 2 + 1], &p1, 4);
            }
            uint4* hp = (uint4*)(g_h1h + (size_t)row * HD1 + half * 32);
#pragma unroll
            for (int q = 0; q < 4; q++)
                hp[q] = make_uint4(packed[q * 4], packed[q * 4 + 1],
                                   packed[q * 4 + 2], packed[q * 4 + 3]);
            float ss[4], sd[4];
#pragma unroll
            for (int hh = 0; hh < 4; hh++) {
                int h = half * 4 + hh;
                float s0 = 0.f, s1 = 0.f;
#pragma unroll
                for (int j = 0; j < 8; j++) {
                    float f = vals[hh * 8 + j];
                    s0 += f * __ldg(a1_src + h * 8 + j);
                    s1 += f * __ldg(a1_dst + h * 8 + j);
                }
                ss[hh] = s0; sd[hh] = s1;
            }
            *(float4*)(g_s1src + (size_t)row * 8 + half * 4) = make_float4(ss[0], ss[1], ss[2], ss[3]);
            *(float4*)(g_s1dst + (size_t)row * 8 + half * 4) = make_float4(sd[0], sd[1], sd[2], sd[3]);
        }
    }
}

// ---------------- K2: degree histogram --------------------------------------
__global__ void k_deg(const int* __restrict__ ei, int ne) {
    int i = blockIdx.x * blockDim.x + threadIdx.x;
    if (i < ne) atomicAdd(&g_deg[ei[ne + i]], 1);
}

// ---------------- K3a/b/c: 3-phase coalesced exclusive scan -----------------
__global__ void __launch_bounds__(1024) k_scan1(int n) {
    __shared__ int sh[32];
    int i = blockIdx.x * 1024 + threadIdx.x;
    int v = (i < n) ? g_deg[i] : 0;
#pragma unroll
    for (int o = 16; o > 0; o >>= 1) v += __shfl_xor_sync(0xffffffffu, v, o);
    if ((threadIdx.x & 31) == 0) sh[threadIdx.x >> 5] = v;
    __syncthreads();
    if (threadIdx.x < 32) {
        int s = sh[threadIdx.x];
#pragma unroll
        for (int o = 16; o > 0; o >>= 1) s += __shfl_xor_sync(0xffffffffu, s, o);
        if (threadIdx.x == 0) g_bsum[blockIdx.x] = s;
    }
}
__global__ void k_scan2(int nb) {
    __shared__ int sh[128];
    int t = threadIdx.x;
    int v = (t < nb) ? g_bsum[t] : 0;
    sh[t] = v;
    __syncthreads();
    for (int o = 1; o < 128; o <<= 1) {
        int u = (t >= o) ? sh[t - o] : 0;
        __syncthreads();
        sh[t] += u;
        __syncthreads();
    }
    if (t < nb) g_bpre[t] = sh[t] - v;
}
__global__ void __launch_bounds__(1024) k_scan3(int n) {
    __shared__ int sh[1024];
    int i = blockIdx.x * 1024 + threadIdx.x;
    int t = threadIdx.x;
    int v = (i < n) ? g_deg[i] : 0;
    sh[t] = v;
    __syncthreads();
    for (int o = 1; o < 1024; o <<= 1) {
        int u = (t >= o) ? sh[t - o] : 0;
        __syncthreads();
        sh[t] += u;
        __syncthreads();
    }
    if (i < n) {
        int off = g_bpre[blockIdx.x] + sh[t] - v;
        g_off[i] = off;
        g_pos[i] = off;
        if (i == n - 1) g_off[n] = off + v;
    }
}

// ---------------- K4: fill CSR buckets --------------------------------------
__global__ void k_fill(const int* __restrict__ ei, int ne) {
    int i = blockIdx.x * blockDim.x + threadIdx.x;
    if (i >= ne) return;
    int d = ei[ne + i];
    int p = atomicAdd(&g_pos[d], 1);
    g_srcs[p] = ei[i];
}

// ---------------- K5: layer-1 single-pass gather + ELU -> act (fp16) --------
__global__ void __launch_bounds__(256) k_gather1(const float* __restrict__ b1, int n) {
    int lane = threadIdx.x & 31;
    int h = lane >> 2;
    int nwarps = gridDim.x * 8;
    const __half2* h1h = (const __half2*)g_h1h;
    __half2* acth = (__half2*)g_acth;
    float b1x = __ldg(b1 + 2 * lane);
    float b1y = __ldg(b1 + 2 * lane + 1);

    for (int d = blockIdx.x * 8 + (threadIdx.x >> 5); d < n; d += nwarps) {
        int e0 = g_off[d], e1 = g_off[d + 1];
        float sdst = g_s1dst[d * 8 + h];

        float z = 0.f, ax = 0.f, ay = 0.f;
        int e = e0;
        for (; e + 4 <= e1; e += 4) {
            int sA = g_srcs[e],     sB = g_srcs[e + 1];
            int sC = g_srcs[e + 2], sD = g_srcs[e + 3];
            float tA = g_s1src[sA * 8 + h] + sdst;
            float tB = g_s1src[sB * 8 + h] + sdst;
            float tC = g_s1src[sC * 8 + h] + sdst;
            float tD = g_s1src[sD * 8 + h] + sdst;
            __half2 vA = h1h[(size_t)sA * 32 + lane];
            __half2 vB = h1h[(size_t)sB * 32 + lane];
            __half2 vC = h1h[(size_t)sC * 32 + lane];
            __half2 vD = h1h[(size_t)sD * 32 + lane];
            float wA = __expf(fmaxf(tA, 0.2f * tA));
            float wB = __expf(fmaxf(tB, 0.2f * tB));
            float wC = __expf(fmaxf(tC, 0.2f * tC));
            float wD = __expf(fmaxf(tD, 0.2f * tD));
            z += (wA + wB) + (wC + wD);
            float2 fA = __half22float2(vA);
            float2 fB = __half22float2(vB);
            float2 fC = __half22float2(vC);
            float2 fD = __half22float2(vD);
            ax += wA * fA.x + wB * fB.x + wC * fC.x + wD * fD.x;
            ay += wA * fA.y + wB * fB.y + wC * fC.y + wD * fD.y;
        }
        for (; e < e1; e++) {
            int s = g_srcs[e];
            float t = g_s1src[s * 8 + h] + sdst;
            float w = __expf(fmaxf(t, 0.2f * t));
            z += w;
            float2 f = __half22float2(h1h[(size_t)s * 32 + lane]);
            ax += w * f.x;
            ay += w * f.y;
        }
        float invz = 1.f / (z + 1e-16f);
        ax = ax * invz + b1x;
        ay = ay * invz + b1y;
        ax = ax > 0.f ? ax : expm1f(ax);
        ay = ay > 0.f ? ay : expm1f(ay);
        acth[(size_t)d * 32 + lane] = __floats2half2_rn(ax, ay);
    }
}

// ---------------- K5b: WMMA fp16 GEMM2 + fused s2 scores + h2 fp16 ----------
__global__ void __launch_bounds__(256) k_gemm2_tc(
        const float* __restrict__ W2, const float* __restrict__ a2_src,
        const float* __restrict__ a2_dst, int n) {
    __shared__ __half Bs[HD1 * C2P];
    __shared__ float Cs[128 * C2P];
    __shared__ float A2s[2 * C2];

    int tid = threadIdx.x, warp = tid >> 5;
    int brow = blockIdx.x * 128;

    for (int i = tid; i < HD1 * C2P; i += 256) {
        int k = i / C2P, c = i % C2P;
        Bs[i] = (c < C2) ? __float2half(W2[k * C2 + c]) : __half(0);
    }
    if (tid < 2 * C2) A2s[tid] = (tid < C2) ? a2_src[tid] : a2_dst[tid - C2];
    __syncthreads();

    wmma::fragment<wmma::accumulator, 16, 16, 16, float> acc[3];
#pragma unroll
    for (int j = 0; j < 3; j++) wmma::fill_fragment(acc[j], 0.f);

    const __half* Abase = g_acth + (size_t)(brow + warp * 16) * HD1;
#pragma unroll
    for (int k16 = 0; k16 < 4; k16++) {
        wmma::fragment<wmma::matrix_a, 16, 16, 16, __half, wmma::row_major> af;
        wmma::load_matrix_sync(af, Abase + k16 * 16, HD1);
#pragma unroll
        for (int j = 0; j < 3; j++) {
            wmma::fragment<wmma::matrix_b, 16, 16, 16, __half, wmma::row_major> bf;
            wmma::load_matrix_sync(bf, Bs + (k16 * 16) * C2P + j * 16, C2P);
            wmma::mma_sync(acc[j], af, bf, acc[j]);
        }
    }
#pragma unroll
    for (int j = 0; j < 3; j++)
        wmma::store_matrix_sync(Cs + (warp * 16) * C2P + j * 16, acc[j], C2P,
                                wmma::mem_row_major);
    __syncthreads();

    {
        int r = tid >> 1, half = tid & 1;
        int row = brow + r;
        if (row < n) {
            const float* cr = Cs + r * C2P + half * 20;
            const float* as = A2s + half * 20;
            const float* ad = A2s + C2 + half * 20;
            float ps = 0.f, pd = 0.f;
            __half2* hp = (__half2*)(g_h2h + (size_t)row * C2) + half * 10;
#pragma unroll
            for (int q = 0; q < 10; q++) {
                float v0 = cr[2 * q], v1 = cr[2 * q + 1];
                ps += v0 * as[2 * q] + v1 * as[2 * q + 1];
                pd += v0 * ad[2 * q] + v1 * ad[2 * q + 1];
                hp[q] = __floats2half2_rn(v0, v1);
            }
            ps += __shfl_xor_sync(0xffffffffu, ps, 1);
            pd += __shfl_xor_sync(0xffffffffu, pd, 1);
            if (half == 0) { g_s2src[row] = ps; g_s2dst[row] = pd; }
        }
    }
}

// ---------------- K6: layer-2 single-pass gather + bias + log_softmax -------
__global__ void __launch_bounds__(256) k_gather2(const float* __restrict__ b2,
                                                 float* __restrict__ out,
                                                 int n) {
    int lane = threadIdx.x & 31;
    int nwarps = gridDim.x * 8;
    float b2v0 = __ldg(b2 + lane);
    float b2v1 = (lane < 8) ? __ldg(b2 + 32 + lane) : 0.f;

    for (int d = blockIdx.x * 8 + (threadIdx.x >> 5); d < n; d += nwarps) {
        int e0 = g_off[d], e1 = g_off[d + 1];
        float sdst = g_s2dst[d];

        float z = 0.f, a0 = 0.f, a1 = 0.f;
        int e = e0;
        for (; e + 4 <= e1; e += 4) {
            int sA = g_srcs[e],     sB = g_srcs[e + 1];
            int sC = g_srcs[e + 2], sD = g_srcs[e + 3];
            float tA = g_s2src[sA] + sdst;
            float tB = g_s2src[sB] + sdst;
            float tC = g_s2src[sC] + sdst;
            float tD = g_s2src[sD] + sdst;
            float hA0 = __half2float(g_h2h[(size_t)sA * C2 + lane]);
            float hB0 = __half2float(g_h2h[(size_t)sB * C2 + lane]);
            float hC0 = __half2float(g_h2h[(size_t)sC * C2 + lane]);
            float hD0 = __half2float(g_h2h[(size_t)sD * C2 + lane]);
            float hA1 = (lane < 8) ? __half2float(g_h2h[(size_t)sA * C2 + 32 + lane]) : 0.f;
            float hB1 = (lane < 8) ? __half2float(g_h2h[(size_t)sB * C2 + 32 + lane]) : 0.f;
            float hC1 = (lane < 8) ? __half2float(g_h2h[(size_t)sC * C2 + 32 + lane]) : 0.f;
            float hD1 = (lane < 8) ? __half2float(g_h2h[(size_t)sD * C2 + 32 + lane]) : 0.f;
            float wA = __expf(fmaxf(tA, 0.2f * tA));
            float wB = __expf(fmaxf(tB, 0.2f * tB));
            float wC = __expf(fmaxf(tC, 0.2f * tC));
            float wD = __expf(fmaxf(tD, 0.2f * tD));
            z += (wA + wB) + (wC + wD);
            a0 += wA * hA0 + wB * hB0 + wC * hC0 + wD * hD0;
            a1 += wA * hA1 + wB * hB1 + wC * hC1 + wD * hD1;
        }
        for (; e < e1; e++) {
            int s = g_srcs[e];
            float t = g_s2src[s] + sdst;
            float w = __expf(fmaxf(t, 0.2f * t));
            z += w;
            a0 += w * __half2float(g_h2h[(size_t)s * C2 + lane]);
            if (lane < 8) a1 += w * __half2float(g_h2h[(size_t)s * C2 + 32 + lane]);
        }
        float invz = 1.f / (z + 1e-16f);
        float o0 = a0 * invz + b2v0;
        float o1 = (lane < 8) ? (a1 * invz + b2v1) : -3.4e38f;

        float mx = fmaxf(o0, o1);
#pragma unroll
        for (int o = 16; o > 0; o >>= 1) mx = fmaxf(mx, __shfl_xor_sync(0xffffffffu, mx, o));
        float se = __expf(o0 - mx) + ((lane < 8) ? __expf(o1 - mx) : 0.f);
#pragma unroll
        for (int o = 16; o > 0; o >>= 1) se += __shfl_xor_sync(0xffffffffu, se, o);
        float L = logf(se) + mx;

        out[(size_t)d * C2 + lane] = o0 - L;
        if (lane < 8) out[(size_t)d * C2 + 32 + lane] = o1 - L;
    }
}

// ---------------- launch -----------------------------------------------------
extern "C" void kernel_launch(void* const* d_in, const int* in_sizes, int n_in,
                              void* d_out, int out_size) {
    const float* x      = (const float*)d_in[0];
    const int*   ei     = (const int*)d_in[1];
    const float* W1     = (const float*)d_in[2];
    const float* a1_src = (const float*)d_in[3];
    const float* a1_dst = (const float*)d_in[4];
    const float* b1     = (const float*)d_in[5];
    const float* W2     = (const float*)d_in[6];
    const float* a2_src = (const float*)d_in[7];
    const float* a2_dst = (const float*)d_in[8];
    const float* b2     = (const float*)d_in[9];
    float* out = (float*)d_out;

    int n  = in_sizes[0] / FIN;   // 100000
    int ne = in_sizes[1] / 2;     // 1600000
    int nb = (n + 1023) / 1024;   // 98

    cudaFuncSetAttribute(k_gemm1_tc, cudaFuncAttributeMaxDynamicSharedMemorySize, GEMM_SMEM);

    // zero degree histogram via memset node (not a kernel launch)
    void* degp = nullptr;
    cudaGetSymbolAddress(&degp, g_deg);
    cudaMemsetAsync(degp, 0, (size_t)n * sizeof(int), 0);

    // k_gemm1_tc stays the 4th kernel launch (ncu capture slot).
    k_deg<<<(ne + 255) / 256, 256>>>(ei, ne);
    k_scan1<<<nb, 1024>>>(n);
    k_scan2<<<1, 128>>>(nb);
    k_gemm1_tc<<<(n + 127) / 128, 256, GEMM_SMEM>>>(x, W1, a1_src, a1_dst, n);
    k_scan3<<<nb, 1024>>>(n);
    k_fill<<<(ne + 255) / 256, 256>>>(ei, ne);
    k_gather1<<<2048, 256>>>(b1, n);
    k_gemm2_tc<<<(n + 127) / 128, 256>>>(W2, a2_src, a2_dst, n);
    k_gather2<<<2048, 256>>>(b2, out, n);

    (void)n_in; (void)out_size;
}

// round 13
// speedup vs baseline: 1.1329x; 1.1329x over previous
#include <cuda_runtime.h>
#include <cuda_bf16.h>
#include <cuda_fp16.h>
#include <mma.h>
#include <cstdint>

using namespace nvcuda;

#define NNODES 100000
#define NEDGES 1600000
#define FIN    256
#define HD1    64
#define H1H    8
#define C2     40
#define C2P    48

// ---------------- scratch (static device globals) ---------------------------
__device__ __half g_h1h[NNODES * HD1];           // layer-1 features, fp16
__device__ __half g_acth[(NNODES + 128) * HD1];  // ELU activations (pad rows zero)
__device__ float g_s1src[NNODES * H1H];
__device__ float g_s1dst[NNODES * H1H];
__device__ __half g_h2h[NNODES * C2];            // layer-2 features, fp16
__device__ float g_s2src[NNODES];
__device__ float g_s2dst[NNODES];
__device__ int   g_deg[NNODES];
__device__ int   g_off[NNODES + 1];
__device__ int   g_pos[NNODES];
__device__ int   g_srcs[NEDGES];
__device__ int   g_bsum[128];
__device__ int   g_bpre[128];

// ---------------- K1: WMMA bf16 split GEMM1 + fused s1 scores (R11 proven) --
#define LDA 72
#define LDB 72
#define OFF_A_HI 0
#define OFF_A_LO 18432
#define OFF_B_HI 36864
#define OFF_B_LO 46080
#define GEMM_SMEM 55296

__global__ void __launch_bounds__(256, 2) k_gemm1_tc(
        const float* __restrict__ x, const float* __restrict__ W1,
        const float* __restrict__ a1_src, const float* __restrict__ a1_dst, int n) {
    extern __shared__ char smem[];
    __nv_bfloat16* As_hi = (__nv_bfloat16*)(smem + OFF_A_HI);
    __nv_bfloat16* As_lo = (__nv_bfloat16*)(smem + OFF_A_LO);
    __nv_bfloat16* Bs_hi = (__nv_bfloat16*)(smem + OFF_B_HI);
    __nv_bfloat16* Bs_lo = (__nv_bfloat16*)(smem + OFF_B_LO);
    float* Cs = (float*)smem;

    int tid = threadIdx.x, warp = tid >> 5;
    int brow = blockIdx.x * 128;
    int m0 = (warp >> 1) * 32;
    int n0 = (warp & 1) * 32;

    wmma::fragment<wmma::accumulator, 16, 16, 16, float> acc[2][2];
#pragma unroll
    for (int i = 0; i < 2; i++)
#pragma unroll
        for (int j = 0; j < 2; j++) wmma::fill_fragment(acc[i][j], 0.f);

    for (int chunk = 0; chunk < 4; chunk++) {
        int k0 = chunk * 64;
#pragma unroll
        for (int t = 0; t < 8; t++) {
            int idx = tid + t * 256;
            int r = idx >> 4, q = idx & 15;
            int grow = brow + r;
            float4 v = make_float4(0.f, 0.f, 0.f, 0.f);
            if (grow < n) v = *(const float4*)(x + (size_t)grow * FIN + k0 + q * 4);
            __nv_bfloat16 h[4], l[4];
            float vv[4] = {v.x, v.y, v.z, v.w};
#pragma unroll
            for (int c = 0; c < 4; c++) {
                h[c] = __float2bfloat16(vv[c]);
                l[c] = __float2bfloat16(vv[c] - __bfloat162float(h[c]));
            }
            int off = r * LDA + q * 4;
            uint2 ph, pl;
            memcpy(&ph, h, 8); memcpy(&pl, l, 8);
            *(uint2*)(As_hi + off) = ph;
            *(uint2*)(As_lo + off) = pl;
        }
#pragma unroll
        for (int t = 0; t < 4; t++) {
            int idx = tid + t * 256;
            int k = idx >> 4, q = idx & 15;
            float4 v = *(const float4*)(W1 + (size_t)(k0 + k) * HD1 + q * 4);
            __nv_bfloat16 h[4], l[4];
            float vv[4] = {v.x, v.y, v.z, v.w};
#pragma unroll
            for (int c = 0; c < 4; c++) {
                h[c] = __float2bfloat16(vv[c]);
                l[c] = __float2bfloat16(vv[c] - __bfloat162float(h[c]));
            }
            int off = k * LDB + q * 4;
            uint2 ph, pl;
            memcpy(&ph, h, 8); memcpy(&pl, l, 8);
            *(uint2*)(Bs_hi + off) = ph;
            *(uint2*)(Bs_lo + off) = pl;
        }
        __syncthreads();

#pragma unroll
        for (int k16 = 0; k16 < 4; k16++) {
            wmma::fragment<wmma::matrix_a, 16, 16, 16, __nv_bfloat16, wmma::row_major> aH[2], aL[2];
            wmma::fragment<wmma::matrix_b, 16, 16, 16, __nv_bfloat16, wmma::row_major> bH[2], bL[2];
#pragma unroll
            for (int i = 0; i < 2; i++) {
                wmma::load_matrix_sync(aH[i], As_hi + (m0 + 16 * i) * LDA + k16 * 16, LDA);
                wmma::load_matrix_sync(aL[i], As_lo + (m0 + 16 * i) * LDA + k16 * 16, LDA);
            }
#pragma unroll
            for (int j = 0; j < 2; j++) {
                wmma::load_matrix_sync(bH[j], Bs_hi + (k16 * 16) * LDB + n0 + 16 * j, LDB);
                wmma::load_matrix_sync(bL[j], Bs_lo + (k16 * 16) * LDB + n0 + 16 * j, LDB);
            }
#pragma unroll
            for (int i = 0; i < 2; i++)
#pragma unroll
                for (int j = 0; j < 2; j++) {
                    wmma::mma_sync(acc[i][j], aH[i], bH[j], acc[i][j]);
                    wmma::mma_sync(acc[i][j], aL[i], bH[j], acc[i][j]);
                    wmma::mma_sync(acc[i][j], aH[i], bL[j], acc[i][j]);
                }
        }
        __syncthreads();
    }

#pragma unroll
    for (int i = 0; i < 2; i++)
#pragma unroll
        for (int j = 0; j < 2; j++)
            wmma::store_matrix_sync(Cs + (m0 + 16 * i) * LDA + n0 + 16 * j,
                                    acc[i][j], LDA, wmma::mem_row_major);
    __syncthreads();

    {
        int r = tid >> 1, half = tid & 1;
        int row = brow + r;
        if (row < n) {
            const float* cr = Cs + r * LDA + half * 32;
            float vals[32];
            uint32_t packed[16];
#pragma unroll
            for (int q = 0; q < 8; q++) {
                float4 v = *(const float4*)(cr + q * 4);
                vals[q * 4 + 0] = v.x; vals[q * 4 + 1] = v.y;
                vals[q * 4 + 2] = v.z; vals[q * 4 + 3] = v.w;
                __half2 p0 = __floats2half2_rn(v.x, v.y);
                __half2 p1 = __floats2half2_rn(v.z, v.w);
                memcpy(&packed[q * 2], &p0, 4);
                memcpy(&packed[q * 2 + 1], &p1, 4);
            }
            uint4* hp = (uint4*)(g_h1h + (size_t)row * HD1 + half * 32);
#pragma unroll
            for (int q = 0; q < 4; q++)
                hp[q] = make_uint4(packed[q * 4], packed[q * 4 + 1],
                                   packed[q * 4 + 2], packed[q * 4 + 3]);
            float ss[4], sd[4];
#pragma unroll
            for (int hh = 0; hh < 4; hh++) {
                int h = half * 4 + hh;
                float s0 = 0.f, s1 = 0.f;
#pragma unroll
                for (int j = 0; j < 8; j++) {
                    float f = vals[hh * 8 + j];
                    s0 += f * __ldg(a1_src + h * 8 + j);
                    s1 += f * __ldg(a1_dst + h * 8 + j);
                }
                ss[hh] = s0; sd[hh] = s1;
            }
            *(float4*)(g_s1src + (size_t)row * 8 + half * 4) = make_float4(ss[0], ss[1], ss[2], ss[3]);
            *(float4*)(g_s1dst + (size_t)row * 8 + half * 4) = make_float4(sd[0], sd[1], sd[2], sd[3]);
        }
    }
}

// ---------------- K2: degree histogram --------------------------------------
__global__ void k_deg(const int* __restrict__ ei, int ne) {
    int i = blockIdx.x * blockDim.x + threadIdx.x;
    if (i < ne) atomicAdd(&g_deg[ei[ne + i]], 1);
}

// ---------------- K3a/b/c: 3-phase coalesced exclusive scan -----------------
__global__ void __launch_bounds__(1024) k_scan1(int n) {
    __shared__ int sh[32];
    int i = blockIdx.x * 1024 + threadIdx.x;
    int v = (i < n) ? g_deg[i] : 0;
#pragma unroll
    for (int o = 16; o > 0; o >>= 1) v += __shfl_xor_sync(0xffffffffu, v, o);
    if ((threadIdx.x & 31) == 0) sh[threadIdx.x >> 5] = v;
    __syncthreads();
    if (threadIdx.x < 32) {
        int s = sh[threadIdx.x];
#pragma unroll
        for (int o = 16; o > 0; o >>= 1) s += __shfl_xor_sync(0xffffffffu, s, o);
        if (threadIdx.x == 0) g_bsum[blockIdx.x] = s;
    }
}
__global__ void k_scan2(int nb) {
    __shared__ int sh[128];
    int t = threadIdx.x;
    int v = (t < nb) ? g_bsum[t] : 0;
    sh[t] = v;
    __syncthreads();
    for (int o = 1; o < 128; o <<= 1) {
        int u = (t >= o) ? sh[t - o] : 0;
        __syncthreads();
        sh[t] += u;
        __syncthreads();
    }
    if (t < nb) g_bpre[t] = sh[t] - v;
}
__global__ void __launch_bounds__(1024) k_scan3(int n) {
    __shared__ int sh[1024];
    int i = blockIdx.x * 1024 + threadIdx.x;
    int t = threadIdx.x;
    int v = (i < n) ? g_deg[i] : 0;
    sh[t] = v;
    __syncthreads();
    for (int o = 1; o < 1024; o <<= 1) {
        int u = (t >= o) ? sh[t - o] : 0;
        __syncthreads();
        sh[t] += u;
        __syncthreads();
    }
    if (i < n) {
        int off = g_bpre[blockIdx.x] + sh[t] - v;
        g_off[i] = off;
        g_pos[i] = off;
        if (i == n - 1) g_off[n] = off + v;
    }
}

// ---------------- K4: fill CSR buckets --------------------------------------
__global__ void k_fill(const int* __restrict__ ei, int ne) {
    int i = blockIdx.x * blockDim.x + threadIdx.x;
    if (i >= ne) return;
    int d = ei[ne + i];
    int p = atomicAdd(&g_pos[d], 1);
    g_srcs[p] = ei[i];
}

// ---------------- K5: layer-1 single-pass gather + ELU -> act (fp16) --------
__global__ void __launch_bounds__(256) k_gather1(const float* __restrict__ b1, int n) {
    int lane = threadIdx.x & 31;
    int h = lane >> 2;
    int nwarps = gridDim.x * 8;
    const __half2* h1h = (const __half2*)g_h1h;
    __half2* acth = (__half2*)g_acth;
    float b1x = __ldg(b1 + 2 * lane);
    float b1y = __ldg(b1 + 2 * lane + 1);

    for (int d = blockIdx.x * 8 + (threadIdx.x >> 5); d < n; d += nwarps) {
        int e0 = g_off[d], e1 = g_off[d + 1];
        float sdst = g_s1dst[d * 8 + h];

        float z = 0.f, ax = 0.f, ay = 0.f;
        int e = e0;
        for (; e + 4 <= e1; e += 4) {
            int sA = g_srcs[e],     sB = g_srcs[e + 1];
            int sC = g_srcs[e + 2], sD = g_srcs[e + 3];
            float tA = g_s1src[sA * 8 + h] + sdst;
            float tB = g_s1src[sB * 8 + h] + sdst;
            float tC = g_s1src[sC * 8 + h] + sdst;
            float tD = g_s1src[sD * 8 + h] + sdst;
            __half2 vA = h1h[(size_t)sA * 32 + lane];
            __half2 vB = h1h[(size_t)sB * 32 + lane];
            __half2 vC = h1h[(size_t)sC * 32 + lane];
            __half2 vD = h1h[(size_t)sD * 32 + lane];
            float wA = __expf(fmaxf(tA, 0.2f * tA));
            float wB = __expf(fmaxf(tB, 0.2f * tB));
            float wC = __expf(fmaxf(tC, 0.2f * tC));
            float wD = __expf(fmaxf(tD, 0.2f * tD));
            z += (wA + wB) + (wC + wD);
            float2 fA = __half22float2(vA);
            float2 fB = __half22float2(vB);
            float2 fC = __half22float2(vC);
            float2 fD = __half22float2(vD);
            ax += wA * fA.x + wB * fB.x + wC * fC.x + wD * fD.x;
            ay += wA * fA.y + wB * fB.y + wC * fC.y + wD * fD.y;
        }
        for (; e < e1; e++) {
            int s = g_srcs[e];
            float t = g_s1src[s * 8 + h] + sdst;
            float w = __expf(fmaxf(t, 0.2f * t));
            z += w;
            float2 f = __half22float2(h1h[(size_t)s * 32 + lane]);
            ax += w * f.x;
            ay += w * f.y;
        }
        float invz = 1.f / (z + 1e-16f);
        ax = ax * invz + b1x;
        ay = ay * invz + b1y;
        ax = ax > 0.f ? ax : expm1f(ax);
        ay = ay > 0.f ? ay : expm1f(ay);
        acth[(size_t)d * 32 + lane] = __floats2half2_rn(ax, ay);
    }
}

// ---------------- K5b: WMMA fp16 GEMM2 + fused s2 scores + h2 fp16 ----------
__global__ void __launch_bounds__(256) k_gemm2_tc(
        const float* __restrict__ W2, const float* __restrict__ a2_src,
        const float* __restrict__ a2_dst, int n) {
    __shared__ __half Bs[HD1 * C2P];
    __shared__ float Cs[128 * C2P];
    __shared__ float A2s[2 * C2];

    int tid = threadIdx.x, warp = tid >> 5;
    int brow = blockIdx.x * 128;

    for (int i = tid; i < HD1 * C2P; i += 256) {
        int k = i / C2P, c = i % C2P;
        Bs[i] = (c < C2) ? __float2half(W2[k * C2 + c]) : __half(0);
    }
    if (tid < 2 * C2) A2s[tid] = (tid < C2) ? a2_src[tid] : a2_dst[tid - C2];
    __syncthreads();

    wmma::fragment<wmma::accumulator, 16, 16, 16, float> acc[3];
#pragma unroll
    for (int j = 0; j < 3; j++) wmma::fill_fragment(acc[j], 0.f);

    const __half* Abase = g_acth + (size_t)(brow + warp * 16) * HD1;
#pragma unroll
    for (int k16 = 0; k16 < 4; k16++) {
        wmma::fragment<wmma::matrix_a, 16, 16, 16, __half, wmma::row_major> af;
        wmma::load_matrix_sync(af, Abase + k16 * 16, HD1);
#pragma unroll
        for (int j = 0; j < 3; j++) {
            wmma::fragment<wmma::matrix_b, 16, 16, 16, __half, wmma::row_major> bf;
            wmma::load_matrix_sync(bf, Bs + (k16 * 16) * C2P + j * 16, C2P);
            wmma::mma_sync(acc[j], af, bf, acc[j]);
        }
    }
#pragma unroll
    for (int j = 0; j < 3; j++)
        wmma::store_matrix_sync(Cs + (warp * 16) * C2P + j * 16, acc[j], C2P,
                                wmma::mem_row_major);
    __syncthreads();

    {
        int r = tid >> 1, half = tid & 1;
        int row = brow + r;
        if (row < n) {
            const float* cr = Cs + r * C2P + half * 20;
            const float* as = A2s + half * 20;
            const float* ad = A2s + C2 + half * 20;
            float ps = 0.f, pd = 0.f;
            __half2* hp = (__half2*)(g_h2h + (size_t)row * C2) + half * 10;
#pragma unroll
            for (int q = 0; q < 10; q++) {
                float v0 = cr[2 * q], v1 = cr[2 * q + 1];
                ps += v0 * as[2 * q] + v1 * as[2 * q + 1];
                pd += v0 * ad[2 * q] + v1 * ad[2 * q + 1];
                hp[q] = __floats2half2_rn(v0, v1);
            }
            ps += __shfl_xor_sync(0xffffffffu, ps, 1);
            pd += __shfl_xor_sync(0xffffffffu, pd, 1);
            if (half == 0) { g_s2src[row] = ps; g_s2dst[row] = pd; }
        }
    }
}

// ---------------- K6: layer-2 single-pass gather + bias + log_softmax -------
__global__ void __launch_bounds__(256) k_gather2(const float* __restrict__ b2,
                                                 float* __restrict__ out,
                                                 int n) {
    int lane = threadIdx.x & 31;
    int nwarps = gridDim.x * 8;
    float b2v0 = __ldg(b2 + lane);
    float b2v1 = (lane < 8) ? __ldg(b2 + 32 + lane) : 0.f;

    for (int d = blockIdx.x * 8 + (threadIdx.x >> 5); d < n; d += nwarps) {
        int e0 = g_off[d], e1 = g_off[d + 1];
        float sdst = g_s2dst[d];

        float z = 0.f, a0 = 0.f, a1 = 0.f;
        int e = e0;
        for (; e + 4 <= e1; e += 4) {
            int sA = g_srcs[e],     sB = g_srcs[e + 1];
            int sC = g_srcs[e + 2], sD = g_srcs[e + 3];
            float tA = g_s2src[sA] + sdst;
            float tB = g_s2src[sB] + sdst;
            float tC = g_s2src[sC] + sdst;
            float tD = g_s2src[sD] + sdst;
            float hA0 = __half2float(g_h2h[(size_t)sA * C2 + lane]);
            float hB0 = __half2float(g_h2h[(size_t)sB * C2 + lane]);
            float hC0 = __half2float(g_h2h[(size_t)sC * C2 + lane]);
            float hD0 = __half2float(g_h2h[(size_t)sD * C2 + lane]);
            float hA1 = (lane < 8) ? __half2float(g_h2h[(size_t)sA * C2 + 32 + lane]) : 0.f;
            float hB1 = (lane < 8) ? __half2float(g_h2h[(size_t)sB * C2 + 32 + lane]) : 0.f;
            float hC1 = (lane < 8) ? __half2float(g_h2h[(size_t)sC * C2 + 32 + lane]) : 0.f;
            float hD1 = (lane < 8) ? __half2float(g_h2h[(size_t)sD * C2 + 32 + lane]) : 0.f;
            float wA = __expf(fmaxf(tA, 0.2f * tA));
            float wB = __expf(fmaxf(tB, 0.2f * tB));
            float wC = __expf(fmaxf(tC, 0.2f * tC));
            float wD = __expf(fmaxf(tD, 0.2f * tD));
            z += (wA + wB) + (wC + wD);
            a0 += wA * hA0 + wB * hB0 + wC * hC0 + wD * hD0;
            a1 += wA * hA1 + wB * hB1 + wC * hC1 + wD * hD1;
        }
        for (; e < e1; e++) {
            int s = g_srcs[e];
            float t = g_s2src[s] + sdst;
            float w = __expf(fmaxf(t, 0.2f * t));
            z += w;
            a0 += w * __half2float(g_h2h[(size_t)s * C2 + lane]);
            if (lane < 8) a1 += w * __half2float(g_h2h[(size_t)s * C2 + 32 + lane]);
        }
        float invz = 1.f / (z + 1e-16f);
        float o0 = a0 * invz + b2v0;
        float o1 = (lane < 8) ? (a1 * invz + b2v1) : -3.4e38f;

        float mx = fmaxf(o0, o1);
#pragma unroll
        for (int o = 16; o > 0; o >>= 1) mx = fmaxf(mx, __shfl_xor_sync(0xffffffffu, mx, o));
        float se = __expf(o0 - mx) + ((lane < 8) ? __expf(o1 - mx) : 0.f);
#pragma unroll
        for (int o = 16; o > 0; o >>= 1) se += __shfl_xor_sync(0xffffffffu, se, o);
        float L = logf(se) + mx;

        out[(size_t)d * C2 + lane] = o0 - L;
        if (lane < 8) out[(size_t)d * C2 + 32 + lane] = o1 - L;
    }
}

// ---------------- launch -----------------------------------------------------
extern "C" void kernel_launch(void* const* d_in, const int* in_sizes, int n_in,
                              void* d_out, int out_size) {
    const float* x      = (const float*)d_in[0];
    const int*   ei     = (const int*)d_in[1];
    const float* W1     = (const float*)d_in[2];
    const float* a1_src = (const float*)d_in[3];
    const float* a1_dst = (const float*)d_in[4];
    const float* b1     = (const float*)d_in[5];
    const float* W2     = (const float*)d_in[6];
    const float* a2_src = (const float*)d_in[7];
    const float* a2_dst = (const float*)d_in[8];
    const float* b2     = (const float*)d_in[9];
    float* out = (float*)d_out;

    int n  = in_sizes[0] / FIN;   // 100000
    int ne = in_sizes[1] / 2;     // 1600000
    int nb = (n + 1023) / 1024;   // 98

    cudaFuncSetAttribute(k_gemm1_tc, cudaFuncAttributeMaxDynamicSharedMemorySize, GEMM_SMEM);

    // Side stream + events, created once on first (uncaptured) call.
    static cudaStream_t s2 = nullptr;
    static cudaEvent_t evFork = nullptr, evJoin = nullptr;
    if (s2 == nullptr) {
        cudaStreamCreateWithFlags(&s2, cudaStreamNonBlocking);
        cudaEventCreateWithFlags(&evFork, cudaEventDisableTiming);
        cudaEventCreateWithFlags(&evJoin, cudaEventDisableTiming);
    }

    // zero degree histogram via memset node (not a kernel launch)
    void* degp = nullptr;
    cudaGetSymbolAddress(&degp, g_deg);
    cudaMemsetAsync(degp, 0, (size_t)n * sizeof(int), 0);

    // Fork: CSR build chain on side stream, GEMM1 concurrently on stream 0.
    cudaEventRecord(evFork, 0);
    cudaStreamWaitEvent(s2, evFork, 0);

    k_deg<<<(ne + 255) / 256, 256, 0, s2>>>(ei, ne);
    k_scan1<<<nb, 1024, 0, s2>>>(n);
    k_scan2<<<1, 128, 0, s2>>>(nb);
    k_scan3<<<nb, 1024, 0, s2>>>(n);
    k_fill<<<(ne + 255) / 256, 256, 0, s2>>>(ei, ne);
    cudaEventRecord(evJoin, s2);

    k_gemm1_tc<<<(n + 127) / 128, 256, GEMM_SMEM, 0>>>(x, W1, a1_src, a1_dst, n);

    // Join: gathers need both GEMM1 (stream 0) and CSR (s2).
    cudaStreamWaitEvent(0, evJoin, 0);

    k_gather1<<<2048, 256>>>(b1, n);
    k_gemm2_tc<<<(n + 127) / 128, 256>>>(W2, a2_src, a2_dst, n);
    k_gather2<<<2048, 256>>>(b2, out, n);

    (void)n_in; (void)out_size;
}